// round 11
// baseline (speedup 1.0000x reference)
#include <cuda_runtime.h>
#include <cstdint>

// B=8192, A=26, NUM_TYPES=3, ANCHOR_DIM=31 (20 anchors, 10 vis, 1 class)
// triples = 8192*26*3 = 638976, each 31 contiguous floats.
// Per triple: x[0..9], z[10..19], vis[20..29], class[30].
#define ANCHOR_DIM 31
#define KSTEPS 10
#define EPSF 1e-9f

constexpr int THREADS = 128;
constexpr int WARPS = THREADS / 32;
constexpr int TRIPLES_PER_TILE = 64;                // two lanes per triple
constexpr int FPT = TRIPLES_PER_TILE * ANCHOR_DIM;  // 1984 floats per array per tile
constexpr int TILE_ARR_BYTES = FPT * 4;             // 7936 B (16B multiple)
constexpr int STAGES = 4;
constexpr int SMEM_BYTES = STAGES * 2 * TILE_ARR_BYTES;  // 63488 B dynamic
constexpr int GRID = 456;                            // 152 SMs x 3 resident: one wave
constexpr int PF_AHEAD = 8;                          // L2 prefetch distance (tiles)

__device__ double g_part0[GRID];
__device__ double g_part1[GRID];
__device__ double g_part2[GRID];
__device__ unsigned int g_count = 0;

__device__ __forceinline__ uint32_t smem_u32(const void* p) {
    return (uint32_t)__cvta_generic_to_shared(p);
}

__device__ __forceinline__ void bulk_g2s(uint32_t dst, const void* src,
                                         uint32_t bytes, uint32_t mbar) {
    asm volatile(
        "cp.async.bulk.shared::cta.global.mbarrier::complete_tx::bytes [%0], [%1], %2, [%3];"
        :: "r"(dst), "l"(src), "r"(bytes), "r"(mbar) : "memory");
}

// Fire-and-forget bulk prefetch into L2 (no SM-side completion tracking).
__device__ __forceinline__ void bulk_prefetch_l2(const void* src, uint32_t bytes) {
    asm volatile("cp.async.bulk.prefetch.L2.global [%0], %1;"
                 :: "l"(src), "r"(bytes) : "memory");
}

__device__ __forceinline__ void mbar_init(uint32_t mbar, uint32_t count) {
    asm volatile("mbarrier.init.shared.b64 [%0], %1;" :: "r"(mbar), "r"(count) : "memory");
}

__device__ __forceinline__ void mbar_expect_tx(uint32_t mbar, uint32_t bytes) {
    asm volatile("mbarrier.arrive.expect_tx.shared.b64 _, [%0], %1;"
                 :: "r"(mbar), "r"(bytes) : "memory");
}

__device__ __forceinline__ void mbar_wait(uint32_t mbar, uint32_t parity) {
    uint32_t done;
    asm volatile(
        "{\n\t.reg .pred p;\n\t"
        "mbarrier.try_wait.parity.acquire.cta.shared::cta.b64 p, [%1], %2;\n\t"
        "selp.b32 %0, 1, 0, p;\n\t}"
        : "=r"(done) : "r"(mbar), "r"(parity) : "memory");
    if (!done) {
        asm volatile(
            "{\n\t.reg .pred P1;\n\t"
            "WL_%=:\n\t"
            "mbarrier.try_wait.parity.acquire.cta.shared::cta.b64 P1, [%0], %1, 0x989680;\n\t"
            "@P1 bra.uni WD_%=;\n\t"
            "bra.uni WL_%=;\n\t"
            "WD_%=:\n\t}"
            :: "r"(mbar), "r"(parity) : "memory");
    }
}

__global__ void __launch_bounds__(THREADS)
loss_kernel(const float* __restrict__ pred, const float* __restrict__ gt,
            float* __restrict__ out, int num_tiles) {
    extern __shared__ float dsm[];  // stage s: [pred FPT | gt FPT]
    __shared__ __align__(8) unsigned long long mbar_store[STAGES];

    const int tid = threadIdx.x;
    const int wid = tid >> 5;
    const int lid = tid & 31;
    const uint32_t mb_base = smem_u32(&mbar_store[0]);

    if (tid == 0) {
#pragma unroll
        for (int s = 0; s < STAGES; s++) mbar_init(mb_base + 8 * s, 1);
    }
    __syncthreads();

    // Contiguous per-block partition: block b owns tiles [start, end).
    const int base_cnt = num_tiles / GRID;
    const int rem = num_tiles % GRID;
    const int b = blockIdx.x;
    const int start = b * base_cnt + (b < rem ? b : rem);
    const int end = start + base_cnt + (b < rem ? 1 : 0);

    auto issue = [&](int tile, int s) {
        uint32_t mb = mb_base + 8 * s;
        uint32_t dst = smem_u32(dsm) + s * 2 * TILE_ARR_BYTES;
        mbar_expect_tx(mb, 2 * TILE_ARR_BYTES);
        bulk_g2s(dst, pred + (size_t)tile * FPT, TILE_ARR_BYTES, mb);
        bulk_g2s(dst + TILE_ARR_BYTES, gt + (size_t)tile * FPT, TILE_ARR_BYTES, mb);
    };

    auto prefetch = [&](int tile) {
        bulk_prefetch_l2(pred + (size_t)tile * FPT, TILE_ARR_BYTES);
        bulk_prefetch_l2(gt + (size_t)tile * FPT, TILE_ARR_BYTES);
    };

    // Prologue: prefetch the whole lookahead window, then fill TMA stages.
    if (tid == 0) {
        for (int k = 0; k < PF_AHEAD && start + k < end; k++) prefetch(start + k);
#pragma unroll
        for (int k = 0; k < STAGES - 1; k++)
            if (start + k < end) issue(start + k, k);
    }

    const int t = tid & 63;          // triple within tile
    const int h = tid >> 6;          // which 5 of the 10 K-steps
    const int jb = 5 * h;

    float s0 = 0.0f, s1 = 0.0f, s2 = 0.0f;
    uint32_t phases = 0;             // per-stage parity bits
    int i = 0;

    for (int tile = start; tile < end; tile++, i++) {
        const int stage = i & (STAGES - 1);
        mbar_wait(mb_base + 8 * stage, (phases >> stage) & 1u);
        phases ^= (1u << stage);

        // Keep DRAM->L2 running deep ahead, then demand-fetch (L2 hit) the
        // i+3-th tile into the stage freed at iteration i-1.
        if (tid == 0) {
            int pf = tile + PF_AHEAD;
            if (pf < end) prefetch(pf);
            int nt = tile + (STAGES - 1);
            if (nt < end) issue(nt, (i + STAGES - 1) & (STAGES - 1));
        }

        // Two lanes per triple; stride 31 coprime with 32 banks -> conflict-free.
        const float* tp = dsm + stage * 2 * FPT + t * ANCHOR_DIM;
        const float* tg = tp + FPT;

        float gvis[5];
#pragma unroll
        for (int jj = 0; jj < 5; jj++) {
            int j = jb + jj;
            float g = tg[2 * KSTEPS + j];
            float p = tp[2 * KSTEPS + j];
            gvis[jj] = g;
            s0 += g * __log2f(p + EPSF) + (1.0f - g + EPSF) * __log2f(1.0f - p + EPSF);
        }
        float gcls = tg[3 * KSTEPS];     // same addr both halves: broadcast
        if (h == 0) {                    // class BCE counted once per triple
            float pcls = tp[3 * KSTEPS];
            s1 += gcls * __log2f(pcls + EPSF) + (1.0f - gcls) * __log2f(1.0f - pcls + EPSF);
        }
        // |c*d| == |c|*|d| exactly; c = gcls*gvis >= 0.
#pragma unroll
        for (int jj = 0; jj < 5; jj++) {
            int j = jb + jj;
            float c = gcls * gvis[jj];
            s2 += c * (fabsf(tp[j] - tg[j]) + fabsf(tp[KSTEPS + j] - tg[KSTEPS + j]));
        }

        __syncthreads();  // all threads done reading this stage before refill
    }

    // Block reduction (cold path).
#pragma unroll
    for (int o = 16; o > 0; o >>= 1) {
        s0 += __shfl_xor_sync(0xffffffffu, s0, o);
        s1 += __shfl_xor_sync(0xffffffffu, s1, o);
        s2 += __shfl_xor_sync(0xffffffffu, s2, o);
    }
    __shared__ float red[3][WARPS];
    if (lid == 0) { red[0][wid] = s0; red[1][wid] = s1; red[2][wid] = s2; }
    __syncthreads();

    __shared__ bool is_last;
    if (tid == 0) {
        float a0 = 0.0f, a1 = 0.0f, a2 = 0.0f;
#pragma unroll
        for (int w = 0; w < WARPS; w++) { a0 += red[0][w]; a1 += red[1][w]; a2 += red[2][w]; }
        g_part0[blockIdx.x] = (double)a0;
        g_part1[blockIdx.x] = (double)a1;
        g_part2[blockIdx.x] = (double)a2;
        __threadfence();
        unsigned int c = atomicAdd(&g_count, 1u);
        is_last = (c == gridDim.x - 1);
    }
    __syncthreads();
    if (!is_last) return;

    // Last block folds all per-block partials and writes the 4 outputs.
    __threadfence();
    double a0 = 0.0, a1 = 0.0, a2 = 0.0;
    for (int k = tid; k < gridDim.x; k += THREADS) {
        a0 += g_part0[k];
        a1 += g_part1[k];
        a2 += g_part2[k];
    }
#pragma unroll
    for (int o = 16; o > 0; o >>= 1) {
        a0 += __shfl_xor_sync(0xffffffffu, a0, o);
        a1 += __shfl_xor_sync(0xffffffffu, a1, o);
        a2 += __shfl_xor_sync(0xffffffffu, a2, o);
    }
    __shared__ double dred[3][WARPS];
    if (lid == 0) { dred[0][wid] = a0; dred[1][wid] = a1; dred[2][wid] = a2; }
    __syncthreads();
    if (tid == 0) {
        double t0d = 0.0, t1d = 0.0, t2d = 0.0;
#pragma unroll
        for (int w = 0; w < WARPS; w++) { t0d += dred[0][w]; t1d += dred[1][w]; t2d += dred[2][w]; }
        const double LN2 = 0.6931471805599453;
        float l0 = (float)(-t0d * LN2 / (double)KSTEPS);
        float l1 = (float)(-t1d * LN2);
        float l2 = (float)(t2d);
        out[0] = l0 + l1 + l2;
        out[1] = l0;
        out[2] = l1;
        out[3] = l2;
        g_count = 0;  // self-reset -> deterministic across graph replays
    }
}

extern "C" void kernel_launch(void* const* d_in, const int* in_sizes, int n_in,
                              void* d_out, int out_size) {
    const float* pred = (const float*)d_in[0];
    const float* gt   = (const float*)d_in[1];
    // d_in[2..5] (hcam/pitch) are unused by the reference.

    int total_floats = in_sizes[0];                                    // 19,808,256
    int num_tiles = total_floats / (ANCHOR_DIM * TRIPLES_PER_TILE);    // 9,984

    cudaFuncSetAttribute(loss_kernel, cudaFuncAttributeMaxDynamicSharedMemorySize,
                         SMEM_BYTES);
    loss_kernel<<<GRID, THREADS, SMEM_BYTES>>>(pred, gt, (float*)d_out, num_tiles);
}

// round 12
// speedup vs baseline: 1.0119x; 1.0119x over previous
#include <cuda_runtime.h>
#include <cstdint>

// B=8192, A=26, NUM_TYPES=3, ANCHOR_DIM=31 (20 anchors, 10 vis, 1 class)
// triples = 8192*26*3 = 638976, each 31 contiguous floats.
// Layout per triple: x[0..9], z[10..19], vis[20..29], class[30].
#define ANCHOR_DIM 31
#define KSTEPS 10
#define EPSF 1e-9f

constexpr int THREADS = 128;
constexpr int WARPS = THREADS / 32;                 // 4
constexpr int TRIPLES_PER_WTILE = 16;               // two lanes per triple
constexpr int FPW = TRIPLES_PER_WTILE * ANCHOR_DIM; // 496 floats per array per warp-tile
constexpr int V4W = FPW / 4;                        // 124 float4s per array
constexpr int STAGES = 2;
constexpr int WARP_SMEM_FLOATS = STAGES * 2 * FPW;  // 1984 floats = 7936 B / warp
constexpr int SMEM_BYTES = WARPS * WARP_SMEM_FLOATS * 4;  // 31744 B / block
constexpr int BLOCKS_PER_SM = 7;                    // 7 * 31744 = 222 KB < 228 KB
constexpr int GRID = 152 * BLOCKS_PER_SM;           // 1064: exactly one wave

__device__ double g_part0[GRID];
__device__ double g_part1[GRID];
__device__ double g_part2[GRID];
__device__ unsigned int g_count = 0;

__device__ __forceinline__ void cp16(float* smem_dst, const float4* gsrc) {
    uint32_t s = (uint32_t)__cvta_generic_to_shared(smem_dst);
    asm volatile("cp.async.cg.shared.global [%0], [%1], 16;" :: "r"(s), "l"(gsrc));
}

__global__ void __launch_bounds__(THREADS, BLOCKS_PER_SM)
loss_kernel(const float* __restrict__ pred, const float* __restrict__ gt,
            float* __restrict__ out, int num_tiles) {
    extern __shared__ float dsm[];
    const int wid = threadIdx.x >> 5;
    const int lid = threadIdx.x & 31;

    float* wbuf = dsm + wid * WARP_SMEM_FLOATS;      // warp-private, 2 stages

    const int gwarp = blockIdx.x * WARPS + wid;      // 0..4255
    const int wstride = GRID * WARPS;                // 4256

    // Issue one 16-triple warp-tile into a stage (both arrays), one group/thread.
    auto issue = [&](int t, int stage) {
        float* sp = wbuf + stage * (2 * FPW);
        float* sg = sp + FPW;
        const float4* p4 = reinterpret_cast<const float4*>(pred) + (size_t)t * V4W;
        const float4* g4 = reinterpret_cast<const float4*>(gt) + (size_t)t * V4W;
#pragma unroll
        for (int i = lid; i < V4W; i += 32) {
            cp16(sp + 4 * i, p4 + i);
            cp16(sg + 4 * i, g4 + i);
        }
        asm volatile("cp.async.commit_group;" ::: "memory");
    };

    float s0 = 0.0f, s1 = 0.0f, s2 = 0.0f;

    // Fill pipeline.
    if (gwarp < num_tiles)            issue(gwarp, 0);
    if (gwarp + wstride < num_tiles)  issue(gwarp + wstride, 1);

    const int h = lid >> 4;          // half-id: which 5 of the 10 K-steps
    const int t = lid & 15;          // triple within tile
    const int jb = 5 * h;

    int stage = 0;
    for (int tile = gwarp; tile < num_tiles; tile += wstride) {
        const bool has_next = (tile + wstride < num_tiles);
        if (has_next) {
            asm volatile("cp.async.wait_group 1;" ::: "memory");
        } else {
            asm volatile("cp.async.wait_group 0;" ::: "memory");
        }
        __syncwarp();

        const float* tp = wbuf + stage * (2 * FPW) + t * ANCHOR_DIM;
        const float* tg = tp + FPW;

        // Each lane does 5 of the 10 K-steps of its triple.
        float gvis[5];
#pragma unroll
        for (int jj = 0; jj < 5; jj++) {
            int j = jb + jj;
            float g = tg[2 * KSTEPS + j];
            float p = tp[2 * KSTEPS + j];
            gvis[jj] = g;
            s0 += g * __log2f(p + EPSF) + (1.0f - g + EPSF) * __log2f(1.0f - p + EPSF);
        }
        // Class BCE split across the two half-lanes of this triple:
        // h=0 contributes gcls*log2(pcls+eps), h=1 contributes (1-gcls)*log2(1-pcls+eps).
        float gcls = tg[3 * KSTEPS];                 // same addr both halves: broadcast
        float pcls = tp[3 * KSTEPS];
        if (h == 0) s1 += gcls * __log2f(pcls + EPSF);
        else        s1 += (1.0f - gcls) * __log2f(1.0f - pcls + EPSF);

        // |c*d| == |c|*|d| exactly; c = gcls*gvis >= 0.
#pragma unroll
        for (int jj = 0; jj < 5; jj++) {
            int j = jb + jj;
            float c = gcls * gvis[jj];
            s2 += c * (fabsf(tp[j] - tg[j]) + fabsf(tp[KSTEPS + j] - tg[KSTEPS + j]));
        }

        __syncwarp();  // all lanes done reading before the refill overwrites
        if (has_next && tile + 2 * wstride < num_tiles) issue(tile + 2 * wstride, stage);
        stage ^= 1;
    }

    // Block reduction (cold path).
#pragma unroll
    for (int o = 16; o > 0; o >>= 1) {
        s0 += __shfl_xor_sync(0xffffffffu, s0, o);
        s1 += __shfl_xor_sync(0xffffffffu, s1, o);
        s2 += __shfl_xor_sync(0xffffffffu, s2, o);
    }
    __shared__ float red[3][WARPS];
    if (lid == 0) { red[0][wid] = s0; red[1][wid] = s1; red[2][wid] = s2; }
    __syncthreads();

    __shared__ bool is_last;
    if (threadIdx.x == 0) {
        float a0 = 0.0f, a1 = 0.0f, a2 = 0.0f;
#pragma unroll
        for (int w = 0; w < WARPS; w++) { a0 += red[0][w]; a1 += red[1][w]; a2 += red[2][w]; }
        g_part0[blockIdx.x] = (double)a0;
        g_part1[blockIdx.x] = (double)a1;
        g_part2[blockIdx.x] = (double)a2;
        __threadfence();
        unsigned int c = atomicAdd(&g_count, 1u);
        is_last = (c == gridDim.x - 1);
    }
    __syncthreads();
    if (!is_last) return;

    // Last block folds all per-block partials and writes the 4 outputs.
    __threadfence();
    double a0 = 0.0, a1 = 0.0, a2 = 0.0;
    for (int i = threadIdx.x; i < gridDim.x; i += THREADS) {
        a0 += g_part0[i];
        a1 += g_part1[i];
        a2 += g_part2[i];
    }
#pragma unroll
    for (int o = 16; o > 0; o >>= 1) {
        a0 += __shfl_xor_sync(0xffffffffu, a0, o);
        a1 += __shfl_xor_sync(0xffffffffu, a1, o);
        a2 += __shfl_xor_sync(0xffffffffu, a2, o);
    }
    __shared__ double dred[3][WARPS];
    if (lid == 0) { dred[0][wid] = a0; dred[1][wid] = a1; dred[2][wid] = a2; }
    __syncthreads();
    if (threadIdx.x == 0) {
        double t0 = 0.0, t1 = 0.0, t2 = 0.0;
#pragma unroll
        for (int w = 0; w < WARPS; w++) { t0 += dred[0][w]; t1 += dred[1][w]; t2 += dred[2][w]; }
        const double LN2 = 0.6931471805599453;
        float l0 = (float)(-t0 * LN2 / (double)KSTEPS);
        float l1 = (float)(-t1 * LN2);
        float l2 = (float)(t2);
        out[0] = l0 + l1 + l2;
        out[1] = l0;
        out[2] = l1;
        out[3] = l2;
        g_count = 0;  // self-reset -> deterministic across graph replays
    }
}

extern "C" void kernel_launch(void* const* d_in, const int* in_sizes, int n_in,
                              void* d_out, int out_size) {
    const float* pred = (const float*)d_in[0];
    const float* gt   = (const float*)d_in[1];
    // d_in[2..5] (hcam/pitch) are unused by the reference.

    int total_floats = in_sizes[0];                                   // 19,808,256
    int num_tiles = total_floats / (ANCHOR_DIM * TRIPLES_PER_WTILE);  // 39,936

    cudaFuncSetAttribute(loss_kernel, cudaFuncAttributeMaxDynamicSharedMemorySize,
                         SMEM_BYTES);
    loss_kernel<<<GRID, THREADS, SMEM_BYTES>>>(pred, gt, (float*)d_out, num_tiles);
}

// round 13
// speedup vs baseline: 1.0138x; 1.0018x over previous
#include <cuda_runtime.h>
#include <cstdint>

// B=8192, A=26, NUM_TYPES=3, ANCHOR_DIM=31 (20 anchors, 10 vis, 1 class)
// triples = 8192*26*3 = 638976, each 31 contiguous floats.
// Layout per triple: x[0..9], z[10..19], vis[20..29], class[30].
#define ANCHOR_DIM 31
#define KSTEPS 10
#define EPSF 1e-9f

constexpr int THREADS = 128;
constexpr int WARPS = THREADS / 32;                 // 4
constexpr int TRIPLES_PER_WTILE = 16;               // two lanes per triple
constexpr int FPW = TRIPLES_PER_WTILE * ANCHOR_DIM; // 496 floats per array per warp-tile
constexpr int V4W = FPW / 4;                        // 124 float4s per array
constexpr int STAGES = 2;
constexpr int WARP_SMEM_FLOATS = STAGES * 2 * FPW;  // 1984 floats = 7936 B / warp
constexpr int SMEM_BYTES = WARPS * WARP_SMEM_FLOATS * 4;  // 31744 B / block
constexpr int BLOCKS_PER_SM = 7;                    // 7 * 31744 = 222 KB < 228 KB
constexpr int GRID = 152 * BLOCKS_PER_SM;           // 1064: exactly one wave

__device__ double g_part0[GRID];
__device__ double g_part1[GRID];
__device__ double g_part2[GRID];
__device__ unsigned int g_count = 0;

__device__ __forceinline__ void cp16(float* smem_dst, const float4* gsrc) {
    uint32_t s = (uint32_t)__cvta_generic_to_shared(smem_dst);
    asm volatile("cp.async.cg.shared.global [%0], [%1], 16;" :: "r"(s), "l"(gsrc));
}

__global__ void __launch_bounds__(THREADS, BLOCKS_PER_SM)
loss_kernel(const float* __restrict__ pred, const float* __restrict__ gt,
            float* __restrict__ out, int num_tiles) {
    extern __shared__ float dsm[];
    const int wid = threadIdx.x >> 5;
    const int lid = threadIdx.x & 31;

    float* wbuf = dsm + wid * WARP_SMEM_FLOATS;      // warp-private, 2 stages

    const int gwarp = blockIdx.x * WARPS + wid;      // 0..4255
    const int wstride = GRID * WARPS;                // 4256

    // Issue one 16-triple warp-tile into a stage (both arrays), one group/thread.
    auto issue = [&](int t, int stage) {
        float* sp = wbuf + stage * (2 * FPW);
        float* sg = sp + FPW;
        const float4* p4 = reinterpret_cast<const float4*>(pred) + (size_t)t * V4W;
        const float4* g4 = reinterpret_cast<const float4*>(gt) + (size_t)t * V4W;
#pragma unroll 4
        for (int i = lid; i < V4W; i += 32) {
            cp16(sp + 4 * i, p4 + i);
            cp16(sg + 4 * i, g4 + i);
        }
        asm volatile("cp.async.commit_group;" ::: "memory");
    };

    float s0 = 0.0f, s1 = 0.0f, s2 = 0.0f;

    // Fill pipeline.
    if (gwarp < num_tiles)            issue(gwarp, 0);
    if (gwarp + wstride < num_tiles)  issue(gwarp + wstride, 1);

    const int h = lid >> 4;          // half-id: which 5 of the 10 K-steps
    const int t = lid & 15;          // triple within tile
    const int jb = 5 * h;

    int stage = 0;
    for (int tile = gwarp; tile < num_tiles; tile += wstride) {
        const bool has_next = (tile + wstride < num_tiles);
        if (has_next) {
            asm volatile("cp.async.wait_group 1;" ::: "memory");
        } else {
            asm volatile("cp.async.wait_group 0;" ::: "memory");
        }
        __syncwarp();

        const float* tp = wbuf + stage * (2 * FPW) + t * ANCHOR_DIM;
        const float* tg = tp + FPW;

        // Each lane does 5 of the 10 K-steps of its triple.
        float gvis[5];
#pragma unroll
        for (int jj = 0; jj < 5; jj++) {
            int j = jb + jj;
            float g = tg[2 * KSTEPS + j];
            float p = tp[2 * KSTEPS + j];
            gvis[jj] = g;
            s0 += g * __log2f(p + EPSF) + (1.0f - g + EPSF) * __log2f(1.0f - p + EPSF);
        }
        float gcls = tg[3 * KSTEPS];                 // same addr both halves: broadcast
        if (h == 0) {                                // class BCE counted once per triple
            float pcls = tp[3 * KSTEPS];
            s1 += gcls * __log2f(pcls + EPSF) + (1.0f - gcls) * __log2f(1.0f - pcls + EPSF);
        }
        // |c*d| == |c|*|d| exactly; c = gcls*gvis >= 0.
#pragma unroll
        for (int jj = 0; jj < 5; jj++) {
            int j = jb + jj;
            float c = gcls * gvis[jj];
            s2 += c * (fabsf(tp[j] - tg[j]) + fabsf(tp[KSTEPS + j] - tg[KSTEPS + j]));
        }

        __syncwarp();  // all lanes done reading before the refill overwrites
        if (has_next && tile + 2 * wstride < num_tiles) issue(tile + 2 * wstride, stage);
        stage ^= 1;
    }

    // Block reduction (cold path).
#pragma unroll
    for (int o = 16; o > 0; o >>= 1) {
        s0 += __shfl_xor_sync(0xffffffffu, s0, o);
        s1 += __shfl_xor_sync(0xffffffffu, s1, o);
        s2 += __shfl_xor_sync(0xffffffffu, s2, o);
    }
    __shared__ float red[3][WARPS];
    if (lid == 0) { red[0][wid] = s0; red[1][wid] = s1; red[2][wid] = s2; }
    __syncthreads();

    __shared__ bool is_last;
    if (threadIdx.x == 0) {
        float a0 = 0.0f, a1 = 0.0f, a2 = 0.0f;
#pragma unroll
        for (int w = 0; w < WARPS; w++) { a0 += red[0][w]; a1 += red[1][w]; a2 += red[2][w]; }
        g_part0[blockIdx.x] = (double)a0;
        g_part1[blockIdx.x] = (double)a1;
        g_part2[blockIdx.x] = (double)a2;
        __threadfence();
        unsigned int c = atomicAdd(&g_count, 1u);
        is_last = (c == gridDim.x - 1);
    }
    __syncthreads();
    if (!is_last) return;

    // Last block folds all per-block partials and writes the 4 outputs.
    __threadfence();
    double a0 = 0.0, a1 = 0.0, a2 = 0.0;
    for (int i = threadIdx.x; i < gridDim.x; i += THREADS) {
        a0 += g_part0[i];
        a1 += g_part1[i];
        a2 += g_part2[i];
    }
#pragma unroll
    for (int o = 16; o > 0; o >>= 1) {
        a0 += __shfl_xor_sync(0xffffffffu, a0, o);
        a1 += __shfl_xor_sync(0xffffffffu, a1, o);
        a2 += __shfl_xor_sync(0xffffffffu, a2, o);
    }
    __shared__ double dred[3][WARPS];
    if (lid == 0) { dred[0][wid] = a0; dred[1][wid] = a1; dred[2][wid] = a2; }
    __syncthreads();
    if (threadIdx.x == 0) {
        double t0 = 0.0, t1 = 0.0, t2 = 0.0;
#pragma unroll
        for (int w = 0; w < WARPS; w++) { t0 += dred[0][w]; t1 += dred[1][w]; t2 += dred[2][w]; }
        const double LN2 = 0.6931471805599453;
        float l0 = (float)(-t0 * LN2 / (double)KSTEPS);
        float l1 = (float)(-t1 * LN2);
        float l2 = (float)(t2);
        out[0] = l0 + l1 + l2;
        out[1] = l0;
        out[2] = l1;
        out[3] = l2;
        g_count = 0;  // self-reset -> deterministic across graph replays
    }
}

extern "C" void kernel_launch(void* const* d_in, const int* in_sizes, int n_in,
                              void* d_out, int out_size) {
    const float* pred = (const float*)d_in[0];
    const float* gt   = (const float*)d_in[1];
    // d_in[2..5] (hcam/pitch) are unused by the reference.

    int total_floats = in_sizes[0];                                   // 19,808,256
    int num_tiles = total_floats / (ANCHOR_DIM * TRIPLES_PER_WTILE);  // 39,936

    cudaFuncSetAttribute(loss_kernel, cudaFuncAttributeMaxDynamicSharedMemorySize,
                         SMEM_BYTES);
    loss_kernel<<<GRID, THREADS, SMEM_BYTES>>>(pred, gt, (float*)d_out, num_tiles);
}

// round 14
// speedup vs baseline: 1.0615x; 1.0471x over previous
#include <cuda_runtime.h>
#include <cstdint>

// B=8192, A=26, NUM_TYPES=3, ANCHOR_DIM=31 (20 anchors, 10 vis, 1 class)
// triples = 8192*26*3 = 638976, each 31 contiguous floats.
// Layout per triple: x[0..9], z[10..19], vis[20..29], class[30].
//
// Final configuration (empirical optimum over 13 measured variants):
//  - warp-private 2-stage cp.async.cg pipeline, 16-triple warp-tiles
//  - 2 half-lanes per triple (5 K-steps each) -> 7.9KB staging/warp
//  - 7 blocks/SM (28 warps/SM), single-wave persistent grid of 1064
//  - BCE via MUFU __log2f, scaled by ln2 once in the double-precision finalize
//  - single fused kernel: per-block double partials + last-block reduction
#define ANCHOR_DIM 31
#define KSTEPS 10
#define EPSF 1e-9f

constexpr int THREADS = 128;
constexpr int WARPS = THREADS / 32;                 // 4
constexpr int TRIPLES_PER_WTILE = 16;               // two lanes per triple
constexpr int FPW = TRIPLES_PER_WTILE * ANCHOR_DIM; // 496 floats per array per warp-tile
constexpr int V4W = FPW / 4;                        // 124 float4s per array
constexpr int STAGES = 2;
constexpr int WARP_SMEM_FLOATS = STAGES * 2 * FPW;  // 1984 floats = 7936 B / warp
constexpr int SMEM_BYTES = WARPS * WARP_SMEM_FLOATS * 4;  // 31744 B / block
constexpr int BLOCKS_PER_SM = 7;                    // 7 * 31744 = 222 KB < 228 KB
constexpr int GRID = 152 * BLOCKS_PER_SM;           // 1064: exactly one wave

__device__ double g_part0[GRID];
__device__ double g_part1[GRID];
__device__ double g_part2[GRID];
__device__ unsigned int g_count = 0;

__device__ __forceinline__ void cp16(float* smem_dst, const float4* gsrc) {
    uint32_t s = (uint32_t)__cvta_generic_to_shared(smem_dst);
    asm volatile("cp.async.cg.shared.global [%0], [%1], 16;" :: "r"(s), "l"(gsrc));
}

__global__ void __launch_bounds__(THREADS, BLOCKS_PER_SM)
loss_kernel(const float* __restrict__ pred, const float* __restrict__ gt,
            float* __restrict__ out, int num_tiles) {
    extern __shared__ float dsm[];
    const int wid = threadIdx.x >> 5;
    const int lid = threadIdx.x & 31;

    float* wbuf = dsm + wid * WARP_SMEM_FLOATS;      // warp-private, 2 stages

    const int gwarp = blockIdx.x * WARPS + wid;      // 0..4255
    const int wstride = GRID * WARPS;                // 4256

    // Issue one 16-triple warp-tile into a stage (both arrays), one group/thread.
    auto issue = [&](int t, int stage) {
        float* sp = wbuf + stage * (2 * FPW);
        float* sg = sp + FPW;
        const float4* p4 = reinterpret_cast<const float4*>(pred) + (size_t)t * V4W;
        const float4* g4 = reinterpret_cast<const float4*>(gt) + (size_t)t * V4W;
#pragma unroll 4
        for (int i = lid; i < V4W; i += 32) {
            cp16(sp + 4 * i, p4 + i);
            cp16(sg + 4 * i, g4 + i);
        }
        asm volatile("cp.async.commit_group;" ::: "memory");
    };

    float s0 = 0.0f, s1 = 0.0f, s2 = 0.0f;

    // Fill pipeline.
    if (gwarp < num_tiles)            issue(gwarp, 0);
    if (gwarp + wstride < num_tiles)  issue(gwarp + wstride, 1);

    const int h = lid >> 4;          // half-id: which 5 of the 10 K-steps
    const int t = lid & 15;          // triple within tile
    const int jb = 5 * h;

    int stage = 0;
    for (int tile = gwarp; tile < num_tiles; tile += wstride) {
        const bool has_next = (tile + wstride < num_tiles);
        if (has_next) {
            asm volatile("cp.async.wait_group 1;" ::: "memory");
        } else {
            asm volatile("cp.async.wait_group 0;" ::: "memory");
        }
        __syncwarp();

        const float* tp = wbuf + stage * (2 * FPW) + t * ANCHOR_DIM;
        const float* tg = tp + FPW;

        // Each lane does 5 of the 10 K-steps of its triple.
        float gvis[5];
#pragma unroll
        for (int jj = 0; jj < 5; jj++) {
            int j = jb + jj;
            float g = tg[2 * KSTEPS + j];
            float p = tp[2 * KSTEPS + j];
            gvis[jj] = g;
            s0 += g * __log2f(p + EPSF) + (1.0f - g + EPSF) * __log2f(1.0f - p + EPSF);
        }
        float gcls = tg[3 * KSTEPS];                 // same addr both halves: broadcast
        if (h == 0) {                                // class BCE counted once per triple
            float pcls = tp[3 * KSTEPS];
            s1 += gcls * __log2f(pcls + EPSF) + (1.0f - gcls) * __log2f(1.0f - pcls + EPSF);
        }
        // |c*d| == |c|*|d| exactly; c = gcls*gvis >= 0.
#pragma unroll
        for (int jj = 0; jj < 5; jj++) {
            int j = jb + jj;
            float c = gcls * gvis[jj];
            s2 += c * (fabsf(tp[j] - tg[j]) + fabsf(tp[KSTEPS + j] - tg[KSTEPS + j]));
        }

        __syncwarp();  // all lanes done reading before the refill overwrites
        if (has_next && tile + 2 * wstride < num_tiles) issue(tile + 2 * wstride, stage);
        stage ^= 1;
    }

    // Block reduction (cold path).
#pragma unroll
    for (int o = 16; o > 0; o >>= 1) {
        s0 += __shfl_xor_sync(0xffffffffu, s0, o);
        s1 += __shfl_xor_sync(0xffffffffu, s1, o);
        s2 += __shfl_xor_sync(0xffffffffu, s2, o);
    }
    __shared__ float red[3][WARPS];
    if (lid == 0) { red[0][wid] = s0; red[1][wid] = s1; red[2][wid] = s2; }
    __syncthreads();

    __shared__ bool is_last;
    if (threadIdx.x == 0) {
        float a0 = 0.0f, a1 = 0.0f, a2 = 0.0f;
#pragma unroll
        for (int w = 0; w < WARPS; w++) { a0 += red[0][w]; a1 += red[1][w]; a2 += red[2][w]; }
        g_part0[blockIdx.x] = (double)a0;
        g_part1[blockIdx.x] = (double)a1;
        g_part2[blockIdx.x] = (double)a2;
        __threadfence();
        unsigned int c = atomicAdd(&g_count, 1u);
        is_last = (c == gridDim.x - 1);
    }
    __syncthreads();
    if (!is_last) return;

    // Last block folds all per-block partials and writes the 4 outputs.
    __threadfence();
    double a0 = 0.0, a1 = 0.0, a2 = 0.0;
    for (int i = threadIdx.x; i < gridDim.x; i += THREADS) {
        a0 += g_part0[i];
        a1 += g_part1[i];
        a2 += g_part2[i];
    }
#pragma unroll
    for (int o = 16; o > 0; o >>= 1) {
        a0 += __shfl_xor_sync(0xffffffffu, a0, o);
        a1 += __shfl_xor_sync(0xffffffffu, a1, o);
        a2 += __shfl_xor_sync(0xffffffffu, a2, o);
    }
    __shared__ double dred[3][WARPS];
    if (lid == 0) { dred[0][wid] = a0; dred[1][wid] = a1; dred[2][wid] = a2; }
    __syncthreads();
    if (threadIdx.x == 0) {
        double t0 = 0.0, t1 = 0.0, t2 = 0.0;
#pragma unroll
        for (int w = 0; w < WARPS; w++) { t0 += dred[0][w]; t1 += dred[1][w]; t2 += dred[2][w]; }
        const double LN2 = 0.6931471805599453;
        float l0 = (float)(-t0 * LN2 / (double)KSTEPS);
        float l1 = (float)(-t1 * LN2);
        float l2 = (float)(t2);
        out[0] = l0 + l1 + l2;
        out[1] = l0;
        out[2] = l1;
        out[3] = l2;
        g_count = 0;  // self-reset -> deterministic across graph replays
    }
}

extern "C" void kernel_launch(void* const* d_in, const int* in_sizes, int n_in,
                              void* d_out, int out_size) {
    const float* pred = (const float*)d_in[0];
    const float* gt   = (const float*)d_in[1];
    // d_in[2..5] (hcam/pitch) are unused by the reference.

    int total_floats = in_sizes[0];                                   // 19,808,256
    int num_tiles = total_floats / (ANCHOR_DIM * TRIPLES_PER_WTILE);  // 39,936

    cudaFuncSetAttribute(loss_kernel, cudaFuncAttributeMaxDynamicSharedMemorySize,
                         SMEM_BYTES);
    loss_kernel<<<GRID, THREADS, SMEM_BYTES>>>(pred, gt, (float*)d_out, num_tiles);
}